// round 16
// baseline (speedup 1.0000x reference)
#include <cuda_runtime.h>
#include <cstdint>
#include <math.h>

// ================= problem constants =================
#define B_ 8
#define S_ 4096
#define D_ 1024
#define H_ 16
#define DH_ 64
#define L_ 6
#define F_ 2048
#define V_ 256
#define NSPLIT 32
#define KPS 128      // keys per split: NSPLIT*KPS == S_
#define TILE 16      // keys per smem tile
#define NT (KPS / TILE)
#define PSTR ((size_t)(D_ + 8))  // part stride per (b,split,h)
#define QKPART (B_ * H_ * D_)

// ================= scratch layout (floats) =================
#define OFF_PE   ((size_t)0)                          // S*D
#define OFF_Q0   (OFF_PE   + (size_t)S_ * D_)         // B*D
#define OFF_Q    (OFF_Q0   + (size_t)B_ * D_)         // B*D
#define OFF_QKP  (OFF_Q    + (size_t)B_ * D_)         // 4*B*H*D
#define OFF_PART (OFF_QKP  + (size_t)4 * QKPART)      // B*NSPLIT*H*(D+8)
#define OFF_CTX  (OFF_PART + (size_t)B_ * NSPLIT * H_ * (D_ + 8)) // B*H*D
#define OFF_TA   (OFF_CTX  + (size_t)B_ * H_ * D_)    // B*F
#define OFF_TB   (OFF_TA   + (size_t)B_ * F_)         // B*F
#define OFF_Y    (OFF_TB   + (size_t)B_ * F_)         // B*D
#define OFF_CUR  (OFF_Y    + (size_t)B_ * D_)         // B*D
#define SCRATCH_N (OFF_CUR + (size_t)B_ * D_)

__device__ __align__(16) float g_scratch[SCRATCH_N];
__device__ int g_ctr[16];

// ================= f32x2 helpers =================
__device__ __forceinline__ void fma2(unsigned long long& d,
                                     unsigned long long a,
                                     unsigned long long b) {
    asm("fma.rn.f32x2 %0, %1, %2, %0;" : "+l"(d) : "l"(a), "l"(b));
}
__device__ __forceinline__ void mul2(unsigned long long& d, unsigned long long a) {
    asm("mul.rn.f32x2 %0, %0, %1;" : "+l"(d) : "l"(a));
}
__device__ __forceinline__ float hadd2(unsigned long long v) {
    float lo, hi;
    asm("mov.b64 {%0,%1}, %2;" : "=f"(lo), "=f"(hi) : "l"(v));
    return lo + hi;
}
__device__ __forceinline__ void unpack2(unsigned long long v, float& lo, float& hi) {
    asm("mov.b64 {%0,%1}, %2;" : "=f"(lo), "=f"(hi) : "l"(v));
}
__device__ __forceinline__ unsigned long long bcast2(float a) {
    unsigned long long r;
    asm("mov.b64 %0, {%1,%1};" : "=l"(r) : "f"(a));
    return r;
}

// ================= PE via anchored rotation recurrence (+ fused q0) ==========
__global__ void __launch_bounds__(512) pe_gen_kernel(const float* __restrict__ tgt,
                                                     float* __restrict__ pe,
                                                     float* __restrict__ q0) {
    int j  = threadIdx.x;
    int k0 = blockIdx.x * 16;
    float w = expf((float)(2 * j) * (float)(-9.210340371976184 / 1024.0));
    float sw, cw;
    sincosf(w, &sw, &cw);
    float s, c;
    sincosf((float)k0 * w, &s, &c);
#pragma unroll
    for (int kk = 0; kk < 16; kk++) {
        float2* dst = (float2*)(pe + (size_t)(k0 + kk) * D_ + 2 * j);
        *dst = make_float2(s, c);
        if (k0 + kk == S_ - 1) {
#pragma unroll
            for (int b = 0; b < 8; b++) {
                const float* tr = tgt + ((size_t)b * S_ + S_ - 1) * D_ + 2 * j;
                q0[b * D_ + 2 * j]     = tr[0] + s;
                q0[b * D_ + 2 * j + 1] = tr[1] + c;
            }
        }
        float s2 = fmaf(s, cw, c * sw);
        float c2 = fmaf(c, cw, -s * sw);
        s = s2; c = c2;
    }
}

// ================= batch-8 GEMV, 2 rows/block =================
__global__ void __launch_bounds__(256) gemv2_kernel(
    const float* __restrict__ X, const float* __restrict__ W,
    const float* __restrict__ bias, float* __restrict__ Y,
    int N, int K, int relu, int perHead)
{
    __shared__ float red[8][2][8];
    int tid = threadIdx.x, warp = tid >> 5, lane = tid & 31;
    int n0 = blockIdx.x * 2;
    const float* Xb = X + (perHead ? (size_t)(n0 >> 6) * K : 0);
    size_t bstr = perHead ? (size_t)H_ * K : (size_t)K;

    float acc[2][8];
#pragma unroll
    for (int r = 0; r < 2; r++)
#pragma unroll
        for (int b = 0; b < 8; b++) acc[r][b] = 0.f;

    for (int k = tid * 4; k < K; k += 1024) {
        float4 wv[2];
#pragma unroll
        for (int r = 0; r < 2; r++)
            wv[r] = __ldg((const float4*)(W + (size_t)(n0 + r) * K + k));
        float4 xv[8];
#pragma unroll
        for (int b = 0; b < 8; b++)
            xv[b] = __ldg((const float4*)(Xb + (size_t)b * bstr + k));
#pragma unroll
        for (int r = 0; r < 2; r++)
#pragma unroll
            for (int b = 0; b < 8; b++) {
                acc[r][b] = fmaf(wv[r].x, xv[b].x, acc[r][b]);
                acc[r][b] = fmaf(wv[r].y, xv[b].y, acc[r][b]);
                acc[r][b] = fmaf(wv[r].z, xv[b].z, acc[r][b]);
                acc[r][b] = fmaf(wv[r].w, xv[b].w, acc[r][b]);
            }
    }
#pragma unroll
    for (int r = 0; r < 2; r++)
#pragma unroll
        for (int b = 0; b < 8; b++) {
            float v = acc[r][b];
#pragma unroll
            for (int o = 16; o > 0; o >>= 1) v += __shfl_xor_sync(0xffffffffu, v, o);
            if (lane == 0) red[warp][r][b] = v;
        }
    __syncthreads();
    if (tid < 16) {
        int r = tid >> 3, b = tid & 7;
        float v = 0.f;
#pragma unroll
        for (int w = 0; w < 8; w++) v += red[w][r][b];
        v += bias[n0 + r];
        if (relu) v = fmaxf(v, 0.f);
        Y[(size_t)b * N + n0 + r] = v;
    }
}

// ================= GEMV (N==1024) + fused residual-add + LayerNorm ==========
__global__ void __launch_bounds__(256) gemv_ln_kernel(
    const float* __restrict__ X, const float* __restrict__ W,
    const float* __restrict__ bias, float* __restrict__ Y,
    int K,
    const float* __restrict__ R, const float* __restrict__ lnw,
    const float* __restrict__ lnb, float* __restrict__ out,
    int* __restrict__ ctr)
{
    __shared__ float red[8][2][8];
    int tid = threadIdx.x, warp = tid >> 5, lane = tid & 31;
    int n0 = blockIdx.x * 2;

    float acc[2][8];
#pragma unroll
    for (int r = 0; r < 2; r++)
#pragma unroll
        for (int b = 0; b < 8; b++) acc[r][b] = 0.f;

    for (int k = tid * 4; k < K; k += 1024) {
        float4 wv[2];
#pragma unroll
        for (int r = 0; r < 2; r++)
            wv[r] = __ldg((const float4*)(W + (size_t)(n0 + r) * K + k));
        float4 xv[8];
#pragma unroll
        for (int b = 0; b < 8; b++)
            xv[b] = __ldg((const float4*)(X + (size_t)b * K + k));
#pragma unroll
        for (int r = 0; r < 2; r++)
#pragma unroll
            for (int b = 0; b < 8; b++) {
                acc[r][b] = fmaf(wv[r].x, xv[b].x, acc[r][b]);
                acc[r][b] = fmaf(wv[r].y, xv[b].y, acc[r][b]);
                acc[r][b] = fmaf(wv[r].z, xv[b].z, acc[r][b]);
                acc[r][b] = fmaf(wv[r].w, xv[b].w, acc[r][b]);
            }
    }
#pragma unroll
    for (int r = 0; r < 2; r++)
#pragma unroll
        for (int b = 0; b < 8; b++) {
            float v = acc[r][b];
#pragma unroll
            for (int o = 16; o > 0; o >>= 1) v += __shfl_xor_sync(0xffffffffu, v, o);
            if (lane == 0) red[warp][r][b] = v;
        }
    __syncthreads();
    if (tid < 16) {
        int r = tid >> 3, b = tid & 7;
        float v = 0.f;
#pragma unroll
        for (int w = 0; w < 8; w++) v += red[w][r][b];
        v += bias[n0 + r];
        Y[(size_t)b * D_ + n0 + r] = v;
    }
    // ---- last-block LN epilogue ----
    __threadfence();
    __shared__ int isLast;
    __syncthreads();
    if (tid == 0) {
        int old = atomicAdd(ctr, 1);
        isLast = (old == (int)gridDim.x - 1);
    }
    __syncthreads();
    if (!isLast) return;
    __threadfence();

    int b = warp;               // 8 warps = 8 batches
    float4 v[8];
    float s = 0.f;
#pragma unroll
    for (int j = 0; j < 8; j++) {
        int d = lane * 4 + j * 128;
        float4 yv = *(const float4*)(Y + (size_t)b * D_ + d);
        float4 rv = __ldg((const float4*)(R + (size_t)b * D_ + d));
        v[j] = make_float4(yv.x + rv.x, yv.y + rv.y, yv.z + rv.z, yv.w + rv.w);
        s += v[j].x + v[j].y + v[j].z + v[j].w;
    }
#pragma unroll
    for (int o = 16; o > 0; o >>= 1) s += __shfl_xor_sync(0xffffffffu, s, o);
    float mean = s * (1.f / 1024.f);
    float vs = 0.f;
#pragma unroll
    for (int j = 0; j < 8; j++) {
        float dx = v[j].x - mean, dy = v[j].y - mean, dz = v[j].z - mean, dw = v[j].w - mean;
        vs += dx * dx + dy * dy + dz * dz + dw * dw;
    }
#pragma unroll
    for (int o = 16; o > 0; o >>= 1) vs += __shfl_xor_sync(0xffffffffu, vs, o);
    float rstd = rsqrtf(vs * (1.f / 1024.f) + 1e-5f);
#pragma unroll
    for (int j = 0; j < 8; j++) {
        int d = lane * 4 + j * 128;
        float4 wv = __ldg((const float4*)(lnw + d));
        float4 bv = __ldg((const float4*)(lnb + d));
        float4 o;
        o.x = (v[j].x - mean) * rstd * wv.x + bv.x;
        o.y = (v[j].y - mean) * rstd * wv.y + bv.y;
        o.z = (v[j].z - mean) * rstd * wv.z + bv.z;
        o.w = (v[j].w - mean) * rstd * wv.w + bv.w;
        *(float4*)(out + (size_t)b * D_ + d) = o;
    }
}

// ================= qk partials =================
__global__ void __launch_bounds__(256) qk_split_kernel(const float* __restrict__ Q,
                                                       const float* __restrict__ in_w,
                                                       float* __restrict__ qkp) {
    int h = blockIdx.y, p = blockIdx.z;
    int d = blockIdx.x * 256 + threadIdx.x;
    __shared__ float Qs[8][16];
    for (int i = threadIdx.x; i < 128; i += 256) {
        int b = i >> 4, u = i & 15;
        Qs[b][u] = Q[b * D_ + h * DH_ + p * 16 + u];
    }
    __syncthreads();
    float acc[8];
#pragma unroll
    for (int b = 0; b < 8; b++) acc[b] = 0.f;
    const float* wrow = in_w + (size_t)(D_ + h * DH_ + p * 16) * D_ + d;
    float wbuf[16];
#pragma unroll
    for (int u = 0; u < 16; u++) wbuf[u] = __ldg(wrow + (size_t)u * D_);
#pragma unroll
    for (int u = 0; u < 16; u++)
#pragma unroll
        for (int b = 0; b < 8; b++) acc[b] = fmaf(Qs[b][u], wbuf[u], acc[b]);
#pragma unroll
    for (int b = 0; b < 8; b++)
        qkp[(size_t)p * QKPART + ((size_t)(b * H_ + h)) * D_ + d] = acc[b];
}

// ================= fused flash-decode attention ==============================
// One pass over x = tgt+pe: per-key online softmax + weighted accumulation.
// grid (NSPLIT, B), 256 threads, warp w handles heads 2w, 2w+1.
// part[(b*NSPLIT+split)*H + h] : D floats of acc, then [D]=m, [D+1]=sum.
__global__ void __launch_bounds__(256) flash_kernel(const float* __restrict__ tgt,
                                                    const float* __restrict__ pe,
                                                    const float* __restrict__ qkp,
                                                    float* __restrict__ part) {
    extern __shared__ __align__(16) float xs[];   // TILE*1024 floats = 64KB
    int b = blockIdx.y, split = blockIdx.x;
    int tid = threadIdx.x, warp = tid >> 5, lane = tid & 31;
    int h0 = warp * 2;

    unsigned long long qq[2][16];
#pragma unroll
    for (int hh = 0; hh < 2; hh++) {
        const float* qp = qkp + ((size_t)(b * H_ + h0 + hh)) * D_ + lane * 4;
#pragma unroll
        for (int j = 0; j < 8; j++) {
            float4 q0v = __ldg((const float4*)(qp + j * 128));
            float4 q1v = __ldg((const float4*)(qp + j * 128 + QKPART));
            float4 q2v = __ldg((const float4*)(qp + j * 128 + 2 * QKPART));
            float4 q3v = __ldg((const float4*)(qp + j * 128 + 3 * QKPART));
            float qx = q0v.x + q1v.x + q2v.x + q3v.x;
            float qy = q0v.y + q1v.y + q2v.y + q3v.y;
            float qz = q0v.z + q1v.z + q2v.z + q3v.z;
            float qw = q0v.w + q1v.w + q2v.w + q3v.w;
            unsigned long long lo, hi;
            asm("mov.b64 %0, {%1,%2};" : "=l"(lo) : "f"(qx), "f"(qy));
            asm("mov.b64 %0, {%1,%2};" : "=l"(hi) : "f"(qz), "f"(qw));
            qq[hh][2 * j]     = lo;
            qq[hh][2 * j + 1] = hi;
        }
    }

    float m0 = -1e30f, m1 = -1e30f, sum0 = 0.f, sum1 = 0.f;
    unsigned long long acc[2][16];
#pragma unroll
    for (int hh = 0; hh < 2; hh++)
#pragma unroll
        for (int j = 0; j < 16; j++) acc[hh][j] = 0ull;

    for (int t = 0; t < NT; t++) {
        int k0 = split * KPS + t * TILE;
        __syncthreads();
        for (int i = tid; i < TILE * 256; i += 256) {
            int kk = i >> 8;
            int dq = (i & 255) * 4;
            float4 tv = *(const float4*)(tgt + ((size_t)b * S_ + k0 + kk) * D_ + dq);
            float4 pv = *(const float4*)(pe + (size_t)(k0 + kk) * D_ + dq);
            float4 o = make_float4(tv.x + pv.x, tv.y + pv.y, tv.z + pv.z, tv.w + pv.w);
            *(float4*)&xs[kk * 1024 + dq] = o;
        }
        __syncthreads();
#pragma unroll
        for (int kk = 0; kk < TILE; kk++) {
            const float* xp = &xs[kk * 1024 + lane * 4];
            unsigned long long xv[16];
#pragma unroll
            for (int j = 0; j < 8; j++) {
                ulonglong2 v = *(const ulonglong2*)(xp + j * 128);
                xv[2 * j] = v.x; xv[2 * j + 1] = v.y;
            }
            unsigned long long d0 = 0, d1 = 0, e0 = 0, e1 = 0;
#pragma unroll
            for (int j = 0; j < 8; j++) {
                fma2(d0, qq[0][2 * j],     xv[2 * j]);
                fma2(d1, qq[0][2 * j + 1], xv[2 * j + 1]);
                fma2(e0, qq[1][2 * j],     xv[2 * j]);
                fma2(e1, qq[1][2 * j + 1], xv[2 * j + 1]);
            }
            float sA = hadd2(d0) + hadd2(d1);
            float sB = hadd2(e0) + hadd2(e1);
#pragma unroll
            for (int o = 16; o > 0; o >>= 1) {
                sA += __shfl_xor_sync(0xffffffffu, sA, o);
                sB += __shfl_xor_sync(0xffffffffu, sB, o);
            }
            // head 0 online update
            if (sA > m0) {
                float al = expf((m0 - sA) * 0.125f);
                unsigned long long ap = bcast2(al);
#pragma unroll
                for (int j = 0; j < 16; j++) mul2(acc[0][j], ap);
                sum0 *= al;
                m0 = sA;
            }
            {
                float w = expf((sA - m0) * 0.125f);
                sum0 += w;
                unsigned long long wp = bcast2(w);
#pragma unroll
                for (int j = 0; j < 16; j++) fma2(acc[0][j], wp, xv[j]);
            }
            // head 1 online update
            if (sB > m1) {
                float al = expf((m1 - sB) * 0.125f);
                unsigned long long ap = bcast2(al);
#pragma unroll
                for (int j = 0; j < 16; j++) mul2(acc[1][j], ap);
                sum1 *= al;
                m1 = sB;
            }
            {
                float w = expf((sB - m1) * 0.125f);
                sum1 += w;
                unsigned long long wp = bcast2(w);
#pragma unroll
                for (int j = 0; j < 16; j++) fma2(acc[1][j], wp, xv[j]);
            }
        }
    }
#pragma unroll
    for (int hh = 0; hh < 2; hh++) {
        size_t base = (((size_t)(b * NSPLIT + split)) * H_ + h0 + hh) * PSTR;
#pragma unroll
        for (int j = 0; j < 8; j++) {
            ulonglong2 v; v.x = acc[hh][2 * j]; v.y = acc[hh][2 * j + 1];
            *(ulonglong2*)(part + base + j * 128 + lane * 4) = v;
        }
        if (lane == 0) {
            part[base + D_]     = (hh == 0) ? m0 : m1;
            part[base + D_ + 1] = (hh == 0) ? sum0 : sum1;
        }
    }
}

// ================= combine split-softmax partials =================
// grid = B*H blocks, 256 threads. ctx[b*H+h][d].
__global__ void __launch_bounds__(256) combine_kernel(const float* __restrict__ part,
                                                      float* __restrict__ ctx) {
    int bh = blockIdx.x;
    int b = bh >> 4, h = bh & 15;
    int tid = threadIdx.x;
    __shared__ float fs[NSPLIT];
    __shared__ float invT;
    if (tid < NSPLIT) {
        size_t base = (((size_t)(b * NSPLIT + tid)) * H_ + h) * PSTR;
        float mv = part[base + D_];
        float sv = part[base + D_ + 1];
        float M = mv;
#pragma unroll
        for (int o = 16; o > 0; o >>= 1) M = fmaxf(M, __shfl_xor_sync(0xffffffffu, M, o));
        float f = expf((mv - M) * 0.125f);
        float ts = sv * f;
#pragma unroll
        for (int o = 16; o > 0; o >>= 1) ts += __shfl_xor_sync(0xffffffffu, ts, o);
        fs[tid] = f;
        if (tid == 0) invT = 1.f / ts;
    }
    __syncthreads();
    int d = tid * 4;
    float ax = 0.f, ay = 0.f, az = 0.f, aw = 0.f;
#pragma unroll 8
    for (int sp = 0; sp < NSPLIT; sp++) {
        size_t base = (((size_t)(b * NSPLIT + sp)) * H_ + h) * PSTR;
        float4 v = *(const float4*)(part + base + d);
        float f = fs[sp];
        ax = fmaf(v.x, f, ax); ay = fmaf(v.y, f, ay);
        az = fmaf(v.z, f, az); aw = fmaf(v.w, f, aw);
    }
    float s = invT;
    float4 o = make_float4(ax * s, ay * s, az * s, aw * s);
    *(float4*)(ctx + (size_t)bh * D_ + d) = o;
}

// ================= host =================
extern "C" void kernel_launch(void* const* d_in, const int* in_sizes, int n_in,
                              void* d_out, int out_size) {
    const float* tgt        = (const float*)d_in[0];
    const float* in_proj_w  = (const float*)d_in[1];
    const float* in_proj_b  = (const float*)d_in[2];
    const float* out_proj_w = (const float*)d_in[3];
    const float* out_proj_b = (const float*)d_in[4];
    const float* ln1_w      = (const float*)d_in[5];
    const float* ln1_b      = (const float*)d_in[6];
    const float* lin1_w     = (const float*)d_in[7];
    const float* lin1_b     = (const float*)d_in[8];
    const float* lin2_w     = (const float*)d_in[9];
    const float* lin2_b     = (const float*)d_in[10];
    const float* ln2_w      = (const float*)d_in[11];
    const float* ln2_b      = (const float*)d_in[12];
    const float* w_out      = (const float*)d_in[13];
    const float* b_out      = (const float*)d_in[14];
    float* out = (float*)d_out;

    float* sp = nullptr;
    cudaGetSymbolAddress((void**)&sp, g_scratch);
    int* ctr = nullptr;
    cudaGetSymbolAddress((void**)&ctr, g_ctr);

    float* pe   = sp + OFF_PE;
    float* q0   = sp + OFF_Q0;
    float* Qb   = sp + OFF_Q;
    float* qkp  = sp + OFF_QKP;
    float* part = sp + OFF_PART;
    float* ctx  = sp + OFF_CTX;
    float* tA   = sp + OFF_TA;
    float* tB   = sp + OFF_TB;
    float* Yb   = sp + OFF_Y;
    float* cur  = sp + OFF_CUR;

    static int smemSet = 0;
    if (!smemSet) {
        cudaFuncSetAttribute(flash_kernel,
                             cudaFuncAttributeMaxDynamicSharedMemorySize,
                             TILE * 1024 * sizeof(float));
        smemSet = 1;
    }

    cudaMemsetAsync(ctr, 0, 16 * sizeof(int));

    pe_gen_kernel<<<S_ / 16, 512>>>(tgt, pe, q0);

    // ---- layer 0 attention ----
    gemv2_kernel<<<D_ / 2, 256>>>(q0, in_proj_w, in_proj_b, Qb, D_, D_, 0, 0);
    qk_split_kernel<<<dim3(D_ / 256, H_, 4), 256>>>(Qb, in_proj_w, qkp);
    flash_kernel<<<dim3(NSPLIT, B_), 256, TILE * 1024 * sizeof(float)>>>(tgt, pe, qkp, part);
    combine_kernel<<<B_ * H_, 256>>>(part, ctx);
    gemv2_kernel<<<D_ / 2, 256>>>(ctx, in_proj_w + (size_t)2 * D_ * D_,
                                  in_proj_b + 2 * D_, tA, D_, D_, 0, 1);
    gemv_ln_kernel<<<D_ / 2, 256>>>(tA, out_proj_w, out_proj_b, tB, D_,
                                    q0, ln1_w, ln1_b, Yb, ctr + 0);
    gemv2_kernel<<<F_ / 2, 256>>>(Yb, lin1_w, lin1_b, tA, F_, D_, 1, 0);
    gemv_ln_kernel<<<D_ / 2, 256>>>(tA, lin2_w, lin2_b, tB, F_,
                                    Yb, ln2_w, ln2_b, cur, ctr + 1);

    // ---- layers 1..5 (single-token attention == V projection) ----
    for (int i = 1; i < L_; i++) {
        const float* wv_i  = in_proj_w + (size_t)i * 3 * D_ * D_ + (size_t)2 * D_ * D_;
        const float* bv_i  = in_proj_b + (size_t)i * 3 * D_ + 2 * D_;
        const float* ow_i  = out_proj_w + (size_t)i * D_ * D_;
        const float* ob_i  = out_proj_b + (size_t)i * D_;
        const float* l1w_i = lin1_w + (size_t)i * F_ * D_;
        const float* l1b_i = lin1_b + (size_t)i * F_;
        const float* l2w_i = lin2_w + (size_t)i * D_ * F_;
        const float* l2b_i = lin2_b + (size_t)i * D_;

        gemv2_kernel<<<D_ / 2, 256>>>(cur, wv_i, bv_i, tA, D_, D_, 0, 0);
        gemv_ln_kernel<<<D_ / 2, 256>>>(tA, ow_i, ob_i, tB, D_,
                                        cur, ln1_w + i * D_, ln1_b + i * D_, Yb,
                                        ctr + 2 * i);
        gemv2_kernel<<<F_ / 2, 256>>>(Yb, l1w_i, l1b_i, tA, F_, D_, 1, 0);
        gemv_ln_kernel<<<D_ / 2, 256>>>(tA, l2w_i, l2b_i, tB, F_,
                                        Yb, ln2_w + i * D_, ln2_b + i * D_, cur,
                                        ctr + 2 * i + 1);
    }

    // ---- final projection to vocab ----
    gemv2_kernel<<<V_ / 2, 256>>>(cur, w_out, b_out, out, V_, D_, 0, 0);

    (void)in_sizes; (void)n_in; (void)out_size;
}